// round 9
// baseline (speedup 1.0000x reference)
#include <cuda_runtime.h>
#include <math.h>
#include <stdint.h>

// Problem constants: B=32, T=1024, D=256, H=256
#define BB 32
#define TT 1024
#define DD 256
#define HH 256
#define GRID 888             // 6 CTAs/SM * 148 SMs (co-residency proven in R8)
#define NTHREADS 256
#define TILE_ROWS 16
#define TILE_BYTES (TILE_ROWS * DD * 4)     // 16384
#define TILE_F4    (TILE_BYTES / 16)        // 1024 float4
#define NTILES 2048                          // 64 tiles per batch
#define WORK_MOD (NTILES + GRID)             // 2936 tickets consumed per launch
#define NPART 256                            // partials per batch (4 per tile)

// Scratch (device globals — no allocation allowed)
__device__ __align__(16) float g_partial[BB * NPART * DD];   // 8 MB
__device__ __align__(16) float g_W[BB * DD];
__device__ __align__(16) float g_bias[BB * DD];
__device__ unsigned g_ticket = 0;            // barrier arrival tickets (monotonic)
__device__ volatile unsigned g_gen = 0;      // barrier generation (monotonic)
__device__ unsigned g_work1 = 0;             // phase-1 work-steal counter
__device__ unsigned g_work3 = 0;             // phase-3 work-steal counter

// ---------------------------------------------------------------------------
// PTX helpers: mbarrier + cp.async.bulk (1D, no tensor map needed)
// ---------------------------------------------------------------------------
__device__ __forceinline__ unsigned smem_u32(const void* p) {
    return (unsigned)__cvta_generic_to_shared(p);
}
__device__ __forceinline__ void mbar_init(unsigned a, unsigned cnt) {
    asm volatile("mbarrier.init.shared.b64 [%0], %1;" :: "r"(a), "r"(cnt) : "memory");
}
__device__ __forceinline__ void mbar_expect_tx(unsigned a, unsigned bytes) {
    asm volatile("mbarrier.arrive.expect_tx.shared.b64 _, [%0], %1;"
                 :: "r"(a), "r"(bytes) : "memory");
}
__device__ __forceinline__ void mbar_wait(unsigned a, int phase) {
    asm volatile(
        "{\n\t.reg .pred P;\n\t"
        "W_%=:\n\t"
        "mbarrier.try_wait.parity.acquire.cta.shared::cta.b64 P, [%0], %1, 0x989680;\n\t"
        "@P bra D_%=;\n\t"
        "bra W_%=;\n\t"
        "D_%=:\n\t}"
        :: "r"(a), "r"((unsigned)phase) : "memory");
}
__device__ __forceinline__ void bulk_load(unsigned dst_smem, const void* src_gmem,
                                          unsigned bytes, unsigned mbar) {
    asm volatile(
        "cp.async.bulk.shared::cluster.global.mbarrier::complete_tx::bytes "
        "[%0], [%1], %2, [%3];"
        :: "r"(dst_smem), "l"(src_gmem), "r"(bytes), "r"(mbar) : "memory");
}
__device__ __forceinline__ void bulk_store(void* dst_gmem, unsigned src_smem,
                                           unsigned bytes) {
    asm volatile("cp.async.bulk.global.shared::cta.bulk_group [%0], [%1], %2;"
                 :: "l"(dst_gmem), "r"(src_smem), "r"(bytes) : "memory");
}
__device__ __forceinline__ void bulk_commit()      { asm volatile("cp.async.bulk.commit_group;" ::: "memory"); }
__device__ __forceinline__ void bulk_wait_group1() { asm volatile("cp.async.bulk.wait_group 1;" ::: "memory"); }
__device__ __forceinline__ void bulk_wait_group0() { asm volatile("cp.async.bulk.wait_group 0;" ::: "memory"); }
__device__ __forceinline__ void fence_proxy_async_shared() {
    asm volatile("fence.proxy.async.shared::cta;" ::: "memory");
}

// ---------------------------------------------------------------------------
// Grid barrier (proven R7): ticket arrival, volatile-load spin, never resets.
// Safe: all GRID CTAs wave-1 co-resident (6/SM via __launch_bounds__).
// ---------------------------------------------------------------------------
__device__ __forceinline__ void grid_barrier() {
    __syncthreads();
    if (threadIdx.x == 0) {
        __threadfence();
        unsigned gv = g_gen;
        unsigned t = atomicAdd(&g_ticket, 1u);
        if ((t % GRID) == GRID - 1u) {
            __threadfence();
            g_gen = gv + 1u;
        } else {
            while (g_gen == gv) { __nanosleep(32); }
        }
        __threadfence();
    }
    __syncthreads();
}

__device__ __forceinline__ float gelu_exact(float v) {
    return 0.5f * v * (1.0f + erff(v * 0.70710678118654752f));
}
__device__ __forceinline__ float dot4(float4 a, float4 b) {
    return fmaf(a.x, b.x, fmaf(a.y, b.y, fmaf(a.z, b.z, a.w * b.w)));
}

// ---------------------------------------------------------------------------
// Single persistent kernel: TMA reduce -> MLP -> TMA apply
// ---------------------------------------------------------------------------
__global__ __launch_bounds__(NTHREADS, 6) void fused_kernel(
        const float* __restrict__ x,
        const int* __restrict__ len,
        const float* __restrict__ w1w, const float* __restrict__ w1b,
        const float* __restrict__ w2w, const float* __restrict__ w2b,
        const float* __restrict__ q1w, const float* __restrict__ q1b,
        const float* __restrict__ q2w, const float* __restrict__ q2b,
        float* __restrict__ out) {
    __shared__ __align__(128) float4 buf[2][TILE_F4];         // 32 KB
    __shared__ __align__(8) unsigned long long mbar_s[2];
    __shared__ int slot;
    __shared__ __align__(16) float c_sh[DD];
    __shared__ __align__(16) float h_sh[HH];

    const int tid = threadIdx.x;
    const int d4  = tid & 63;
    const int lt  = tid >> 6;                 // 0..3
    const char* xb  = (const char*)x;
    char*       ob  = (char*)out;

    unsigned mb[2]   = { smem_u32(&mbar_s[0]), smem_u32(&mbar_s[1]) };
    unsigned bufa[2] = { smem_u32(&buf[0][0]), smem_u32(&buf[1][0]) };
    if (tid == 0) { mbar_init(mb[0], 1); mbar_init(mb[1], 1); }
    __syncthreads();
    int ph[2] = {0, 0};                       // mbar parity trackers

    // ---------- Phase 1: partial sums via bulk-load pipeline ----------
    {
        int prev = -1, prev_buf = 0, bufsel = 0;
        for (;;) {
            // work-steal draw (deterministic modulo -> replay-safe)
            __syncthreads();
            if (tid == 0) slot = (int)(atomicAdd(&g_work1, 1u) % WORK_MOD);
            __syncthreads();
            int tile = slot;
            bool valid = tile < NTILES;
            if (valid && tid == 0) {
                mbar_expect_tx(mb[bufsel], TILE_BYTES);
                bulk_load(bufa[bufsel], xb + (size_t)tile * TILE_BYTES,
                          TILE_BYTES, mb[bufsel]);
            }
            if (prev >= 0) {
                mbar_wait(mb[prev_buf], ph[prev_buf]); ph[prev_buf] ^= 1;
                int b = prev >> 6, s = prev & 63;
                float4 acc = make_float4(0.f, 0.f, 0.f, 0.f);
#pragma unroll
                for (int k = 0; k < 4; k++) {
                    float4 v = buf[prev_buf][(k * 4 + lt) * 64 + d4];
                    acc.x += v.x; acc.y += v.y; acc.z += v.z; acc.w += v.w;
                }
                reinterpret_cast<float4*>(g_partial)
                    [((size_t)b * NPART + (s * 4 + lt)) * 64 + d4] = acc;
            }
            if (!valid) break;
            prev = tile; prev_buf = bufsel; bufsel ^= 1;
        }
    }
    grid_barrier();

    // ---------- Phase 2: MLPs on 64 CTAs; others idle at barrier ----------
    if (blockIdx.x < 2 * BB) {
        int b = blockIdx.x >> 1;
        int branch = blockIdx.x & 1;
        const float* m1w = branch ? q1w : w1w;
        const float* m1b = branch ? q1b : w1b;
        const float* m2w = branch ? q2w : w2w;
        const float* m2b = branch ? q2b : w2b;
        float* gout = branch ? g_bias : g_W;

        {
            float s = 0.0f;
#pragma unroll 16
            for (int p = 0; p < NPART; p++)
                s += g_partial[((size_t)b * NPART + p) * DD + tid];
            c_sh[tid] = s / (float)len[b];
        }
        __syncthreads();

        int w = tid >> 5, lane = tid & 31;
        const float4* c4 = reinterpret_cast<const float4*>(c_sh);
        const float4* h4 = reinterpret_cast<const float4*>(h_sh);
#pragma unroll 8
        for (int jj = 0; jj < 32; jj++) {
            int o = w * 32 + jj;
            const float4* row = reinterpret_cast<const float4*>(m1w + (size_t)o * DD);
            float acc = dot4(c4[lane], row[lane]) + dot4(c4[lane + 32], row[lane + 32]);
#pragma unroll
            for (int off = 16; off > 0; off >>= 1)
                acc += __shfl_down_sync(0xFFFFFFFFu, acc, off);
            if (lane == 0) h_sh[o] = gelu_exact(acc + m1b[o]);
        }
        __syncthreads();
#pragma unroll 8
        for (int jj = 0; jj < 32; jj++) {
            int o = w * 32 + jj;
            const float4* row = reinterpret_cast<const float4*>(m2w + (size_t)o * HH);
            float acc = dot4(h4[lane], row[lane]) + dot4(h4[lane + 32], row[lane + 32]);
#pragma unroll
            for (int off = 16; off > 0; off >>= 1)
                acc += __shfl_down_sync(0xFFFFFFFFu, acc, off);
            if (lane == 0) gout[b * DD + o] = acc + m2b[o];
        }
    }
    grid_barrier();

    // ---------- Phase 3: apply, smem in-place, bulk load + bulk store ----------
    {
        const float4* gW4 = reinterpret_cast<const float4*>(g_W);
        const float4* gB4 = reinterpret_cast<const float4*>(g_bias);
        int prev = -1, prev_buf = 0, bufsel = 0, pending = 0;
        bool prev_loaded = false;
        for (;;) {
            __syncthreads();
            if (tid == 0) slot = (int)(atomicAdd(&g_work3, 1u) % WORK_MOD);
            __syncthreads();
            int tile = slot;
            bool valid = tile < NTILES;

            // process prev: compute in place, then bulk-store
            if (prev >= 0) {
                int b = prev >> 6, s = prev & 63, tbase = s * TILE_ROWS;
                int L = __ldg(&len[b]);
                if (prev_loaded) { mbar_wait(mb[prev_buf], ph[prev_buf]); ph[prev_buf] ^= 1; }
                float4 wv = gW4[b * 64 + d4];
#pragma unroll
                for (int k = 0; k < 4; k++) {
                    int rr = k * 4 + lt;
                    int t = tbase + rr;
                    float4 o = make_float4(0.f, 0.f, 0.f, 0.f);
                    if (t < L && prev_loaded) {
                        float4 xv = buf[prev_buf][rr * 64 + d4];
                        o.x = fmaf(xv.x, wv.x, xv.x);
                        o.y = fmaf(xv.y, wv.y, xv.y);
                        o.z = fmaf(xv.z, wv.z, xv.z);
                        o.w = fmaf(xv.w, wv.w, xv.w);
                        if (t == 0) {
                            float4 bv = gB4[b * 64 + d4];
                            o.x += bv.x; o.y += bv.y; o.z += bv.z; o.w += bv.w;
                        }
                    }
                    buf[prev_buf][rr * 64 + d4] = o;
                }
                __syncthreads();
                if (tid == 0) {
                    fence_proxy_async_shared();
                    bulk_store(ob + (size_t)prev * TILE_BYTES, bufa[prev_buf], TILE_BYTES);
                    bulk_commit();
                }
                pending++;
            }
            if (!valid) break;

            // free bufsel (its store was 2 tiles ago), then issue load
            if (pending >= 2) { if (tid == 0) bulk_wait_group1(); pending = 1; }
            int b = tile >> 6, s = tile & 63, tbase = s * TILE_ROWS;
            int L = __ldg(&len[b]);
            bool loaded = (tbase < L);
            if (loaded && tid == 0) {
                mbar_expect_tx(mb[bufsel], TILE_BYTES);
                bulk_load(bufa[bufsel], xb + (size_t)tile * TILE_BYTES,
                          TILE_BYTES, mb[bufsel]);
            }
            prev = tile; prev_buf = bufsel; prev_loaded = loaded; bufsel ^= 1;
        }
        if (tid == 0) bulk_wait_group0();     // drain stores before exit
        __syncthreads();
    }
}

// ---------------------------------------------------------------------------
extern "C" void kernel_launch(void* const* d_in, const int* in_sizes, int n_in,
                              void* d_out, int out_size) {
    const float* x     = (const float*)d_in[0];
    const int*   len_x = (const int*)d_in[1];
    const float* Ww1_w = (const float*)d_in[2];
    const float* Ww1_b = (const float*)d_in[3];
    const float* Ww2_w = (const float*)d_in[4];
    const float* Ww2_b = (const float*)d_in[5];
    const float* Wb1_w = (const float*)d_in[6];
    const float* Wb1_b = (const float*)d_in[7];
    const float* Wb2_w = (const float*)d_in[8];
    const float* Wb2_b = (const float*)d_in[9];
    float* out = (float*)d_out;

    fused_kernel<<<GRID, NTHREADS>>>(
        x, len_x,
        Ww1_w, Ww1_b, Ww2_w, Ww2_b,
        Wb1_w, Wb1_b, Wb2_w, Wb2_b,
        out);
}

// round 10
// speedup vs baseline: 1.9506x; 1.9506x over previous
#include <cuda_runtime.h>
#include <math.h>
#include <stdint.h>

// Problem constants: B=32, T=1024, D=256, H=256
#define BB 32
#define TT 1024
#define DD 256
#define HH 256
#define GRID 148
#define NTHREADS 1024
#define TILE_ROWS 32
#define TILE_BYTES (TILE_ROWS * DD * 4)      // 32768
#define TILES_PER_BATCH (TT / TILE_ROWS)     // 32
#define NBUF 6                                // phase-1 load ring
#define NL 4                                  // phase-3 load buffers (slots 0..3)
#define NS 2                                  // phase-3 store buffers (slots 4..5)
#define DYN_SMEM (NBUF * TILE_BYTES)          // 196608

// Scratch (device globals — no allocation allowed)
__device__ __align__(16) float g_partial[GRID * DD];   // one partial per CTA
__device__ __align__(16) float g_W[BB * DD];
__device__ __align__(16) float g_bias[BB * DD];
__device__ unsigned g_ticket = 0;            // barrier tickets (monotonic)
__device__ volatile unsigned g_gen = 0;      // barrier generation (monotonic)

// ---------------------------------------------------------------------------
// PTX helpers
// ---------------------------------------------------------------------------
__device__ __forceinline__ unsigned smem_u32(const void* p) {
    return (unsigned)__cvta_generic_to_shared(p);
}
__device__ __forceinline__ void mbar_init(unsigned a, unsigned cnt) {
    asm volatile("mbarrier.init.shared.b64 [%0], %1;" :: "r"(a), "r"(cnt) : "memory");
}
__device__ __forceinline__ void mbar_expect_tx(unsigned a, unsigned bytes) {
    asm volatile("mbarrier.arrive.expect_tx.shared.b64 _, [%0], %1;"
                 :: "r"(a), "r"(bytes) : "memory");
}
__device__ __forceinline__ void mbar_wait(unsigned a, int phase) {
    asm volatile(
        "{\n\t.reg .pred P;\n\t"
        "W_%=:\n\t"
        "mbarrier.try_wait.parity.acquire.cta.shared::cta.b64 P, [%0], %1, 0x989680;\n\t"
        "@P bra D_%=;\n\t"
        "bra W_%=;\n\t"
        "D_%=:\n\t}"
        :: "r"(a), "r"((unsigned)phase) : "memory");
}
__device__ __forceinline__ void bulk_load(unsigned dst_smem, const void* src_gmem,
                                          unsigned bytes, unsigned mbar) {
    asm volatile(
        "cp.async.bulk.shared::cluster.global.mbarrier::complete_tx::bytes "
        "[%0], [%1], %2, [%3];"
        :: "r"(dst_smem), "l"(src_gmem), "r"(bytes), "r"(mbar) : "memory");
}
__device__ __forceinline__ void bulk_store(void* dst_gmem, unsigned src_smem,
                                           unsigned bytes) {
    asm volatile("cp.async.bulk.global.shared::cta.bulk_group [%0], [%1], %2;"
                 :: "l"(dst_gmem), "r"(src_smem), "r"(bytes) : "memory");
}
__device__ __forceinline__ void bulk_commit()      { asm volatile("cp.async.bulk.commit_group;" ::: "memory"); }
__device__ __forceinline__ void bulk_wait_group1() { asm volatile("cp.async.bulk.wait_group 1;" ::: "memory"); }
__device__ __forceinline__ void bulk_wait_group0() { asm volatile("cp.async.bulk.wait_group 0;" ::: "memory"); }
__device__ __forceinline__ void fence_proxy_async_shared() {
    asm volatile("fence.proxy.async.shared::cta;" ::: "memory");
}

// ---------------------------------------------------------------------------
// Grid barrier (proven R7): 148 arrivals, plain-load spin, never resets.
// Safe: 148 CTAs, 1/SM -> trivially co-resident.
// ---------------------------------------------------------------------------
__device__ __forceinline__ void grid_barrier() {
    __syncthreads();
    if (threadIdx.x == 0) {
        __threadfence();
        unsigned gv = g_gen;
        unsigned t = atomicAdd(&g_ticket, 1u);
        if ((t % GRID) == GRID - 1u) {
            __threadfence();
            g_gen = gv + 1u;
        } else {
            while (g_gen == gv) { __nanosleep(32); }
        }
        __threadfence();
    }
    __syncthreads();
}

__device__ __forceinline__ float gelu_exact(float v) {
    return 0.5f * v * (1.0f + erff(v * 0.70710678118654752f));
}
__device__ __forceinline__ float dot4(float4 a, float4 b) {
    return fmaf(a.x, b.x, fmaf(a.y, b.y, fmaf(a.z, b.z, a.w * b.w)));
}

extern __shared__ __align__(128) char dynsmem[];

// ---------------------------------------------------------------------------
// Persistent kernel: TMA-pipelined reduce -> MLP -> TMA-pipelined apply
// ---------------------------------------------------------------------------
__global__ __launch_bounds__(NTHREADS, 1) void fused_kernel(
        const float* __restrict__ x,
        const int* __restrict__ len,
        const float* __restrict__ w1w, const float* __restrict__ w1b,
        const float* __restrict__ w2w, const float* __restrict__ w2b,
        const float* __restrict__ q1w, const float* __restrict__ q1b,
        const float* __restrict__ q2w, const float* __restrict__ q2b,
        float* __restrict__ out) {
    __shared__ __align__(16) float c_sh[DD];
    __shared__ __align__(16) float h_sh[HH];
    __shared__ __align__(8) unsigned long long mbar_s[NBUF];

    const int tid = threadIdx.x;
    const int d4  = tid & 63;        // float4 column 0..63
    const int r2  = tid >> 6;        // 0..15: rows r2 and r2+16 of a tile
    const char* xb = (const char*)x;
    char*       ob = (char*)out;

    // Static slab assignment: CTA -> one batch, contiguous tile range.
    const int b   = (blockIdx.x * BB) / GRID;
    const int lo  = (b * GRID + BB - 1) / BB;
    const int hi  = ((b + 1) * GRID + BB - 1) / BB;
    const int idx = blockIdx.x - lo;
    const int n   = hi - lo;
    const int t0  = b * TILES_PER_BATCH + (idx * TILES_PER_BATCH) / n;      // global tile id
    const int t1  = b * TILES_PER_BATCH + ((idx + 1) * TILES_PER_BATCH) / n;
    const int nt  = t1 - t0;

    unsigned mb[NBUF], bufa[NBUF];
#pragma unroll
    for (int k = 0; k < NBUF; k++) {
        mb[k]   = smem_u32(&mbar_s[k]);
        bufa[k] = smem_u32(dynsmem) + k * TILE_BYTES;
    }
    if (tid == 0) {
#pragma unroll
        for (int k = 0; k < NBUF; k++) mbar_init(mb[k], 1);
    }
    __syncthreads();
    int ph[NBUF] = {0, 0, 0, 0, 0, 0};
    float4* const bufs = (float4*)dynsmem;   // bufs + k*2048 = buffer k

    // ---------- Phase 1: reduce x over T via 6-deep TMA ring ----------
    {
        if (tid == 0) {
            for (int j = 0; j < (nt < NBUF ? nt : NBUF); j++) {
                mbar_expect_tx(mb[j], TILE_BYTES);
                bulk_load(bufa[j], xb + (size_t)(t0 + j) * TILE_BYTES, TILE_BYTES, mb[j]);
            }
        }
        float4 acc0 = make_float4(0.f, 0.f, 0.f, 0.f);
        float4 acc1 = make_float4(0.f, 0.f, 0.f, 0.f);
        for (int i = 0; i < nt; i++) {
            int s = i % NBUF;
            mbar_wait(mb[s], ph[s]); ph[s] ^= 1;
            float4 v0 = bufs[s * 2048 + r2 * 64 + d4];
            float4 v1 = bufs[s * 2048 + (r2 + 16) * 64 + d4];
            acc0.x += v0.x; acc0.y += v0.y; acc0.z += v0.z; acc0.w += v0.w;
            acc1.x += v1.x; acc1.y += v1.y; acc1.z += v1.z; acc1.w += v1.w;
            __syncthreads();                       // all done reading slot s
            if (i + NBUF < nt && tid == 0) {
                mbar_expect_tx(mb[s], TILE_BYTES);
                bulk_load(bufa[s], xb + (size_t)(t0 + i + NBUF) * TILE_BYTES, TILE_BYTES, mb[s]);
            }
        }
        // flush: 32 rows -> 1 partial per CTA (scratch in buffer 0; all loads done)
        acc0.x += acc1.x; acc0.y += acc1.y; acc0.z += acc1.z; acc0.w += acc1.w;
        bufs[r2 * 64 + d4] = acc0;
        __syncthreads();
        if (tid < 64) {
            float4 a = make_float4(0.f, 0.f, 0.f, 0.f);
#pragma unroll
            for (int r = 0; r < 16; r++) {
                float4 v = bufs[r * 64 + tid];
                a.x += v.x; a.y += v.y; a.z += v.z; a.w += v.w;
            }
            reinterpret_cast<float4*>(g_partial)[blockIdx.x * 64 + tid] = a;
        }
        __syncthreads();
        // phase-3 prologue loads NOW (independent of MLP) -> pipeline warm at barrier exit
        if (tid == 0) {
            for (int j = 0; j < (nt < NL ? nt : NL); j++) {
                mbar_expect_tx(mb[j], TILE_BYTES);
                bulk_load(bufa[j], xb + (size_t)(t0 + j) * TILE_BYTES, TILE_BYTES, mb[j]);
            }
        }
    }
    grid_barrier();

    // ---------- Phase 2: MLPs on CTAs 0..63 ----------
    if (blockIdx.x < 2 * BB) {
        int bm = blockIdx.x >> 1;
        int branch = blockIdx.x & 1;
        const float* m1w = branch ? q1w : w1w;
        const float* m1b = branch ? q1b : w1b;
        const float* m2w = branch ? q2w : w2w;
        const float* m2b = branch ? q2b : w2b;
        float* gout = branch ? g_bias : g_W;

        if (tid < DD) {
            int lo2 = (bm * GRID + BB - 1) / BB;
            int hi2 = ((bm + 1) * GRID + BB - 1) / BB;
            float s = 0.0f;
            for (int c = lo2; c < hi2; c++) s += g_partial[c * DD + tid];
            c_sh[tid] = s / (float)len[bm];
        }
        __syncthreads();

        int w = tid >> 5, lane = tid & 31;     // 32 warps x 8 outputs
        const float4* c4 = reinterpret_cast<const float4*>(c_sh);
        const float4* h4 = reinterpret_cast<const float4*>(h_sh);
#pragma unroll
        for (int jj = 0; jj < 8; jj++) {
            int o = w * 8 + jj;
            const float4* row = reinterpret_cast<const float4*>(m1w + (size_t)o * DD);
            float acc = dot4(c4[lane], row[lane]) + dot4(c4[lane + 32], row[lane + 32]);
#pragma unroll
            for (int off = 16; off > 0; off >>= 1)
                acc += __shfl_down_sync(0xFFFFFFFFu, acc, off);
            if (lane == 0) h_sh[o] = gelu_exact(acc + m1b[o]);
        }
        __syncthreads();
#pragma unroll
        for (int jj = 0; jj < 8; jj++) {
            int o = w * 8 + jj;
            const float4* row = reinterpret_cast<const float4*>(m2w + (size_t)o * HH);
            float acc = dot4(h4[lane], row[lane]) + dot4(h4[lane + 32], row[lane + 32]);
#pragma unroll
            for (int off = 16; off > 0; off >>= 1)
                acc += __shfl_down_sync(0xFFFFFFFFu, acc, off);
            if (lane == 0) gout[bm * DD + o] = acc + m2b[o];
        }
    }
    grid_barrier();

    // ---------- Phase 3: apply; 4 load bufs + 2 store bufs ----------
    {
        const int L = __ldg(&len[b]);
        float4 wv = reinterpret_cast<const float4*>(g_W)[b * 64 + d4];
        float4 bv = reinterpret_cast<const float4*>(g_bias)[b * 64 + d4];

        for (int i = 0; i < nt; i++) {
            int ls = i % NL;
            int ss = NL + (i % NS);             // store slot 4 or 5
            mbar_wait(mb[ls], ph[ls]); ph[ls] ^= 1;
            if (tid == 0) bulk_wait_group1();   // store buffer (i-NS) drained
            __syncthreads();

            int tbase = (t0 + i) * TILE_ROWS - b * TT;   // 0..992 within batch
            // row r2
            {
                int t = tbase + r2;
                float4 o = make_float4(0.f, 0.f, 0.f, 0.f);
                if (t < L) {
                    float4 xv = bufs[ls * 2048 + r2 * 64 + d4];
                    o.x = fmaf(xv.x, wv.x, xv.x);
                    o.y = fmaf(xv.y, wv.y, xv.y);
                    o.z = fmaf(xv.z, wv.z, xv.z);
                    o.w = fmaf(xv.w, wv.w, xv.w);
                    if (t == 0) { o.x += bv.x; o.y += bv.y; o.z += bv.z; o.w += bv.w; }
                }
                bufs[ss * 2048 + r2 * 64 + d4] = o;
            }
            // row r2+16
            {
                int t = tbase + r2 + 16;
                float4 o = make_float4(0.f, 0.f, 0.f, 0.f);
                if (t < L) {
                    float4 xv = bufs[ls * 2048 + (r2 + 16) * 64 + d4];
                    o.x = fmaf(xv.x, wv.x, xv.x);
                    o.y = fmaf(xv.y, wv.y, xv.y);
                    o.z = fmaf(xv.z, wv.z, xv.z);
                    o.w = fmaf(xv.w, wv.w, xv.w);
                }
                bufs[ss * 2048 + (r2 + 16) * 64 + d4] = o;
            }
            __syncthreads();
            if (tid == 0) {
                fence_proxy_async_shared();
                bulk_store(ob + (size_t)(t0 + i) * TILE_BYTES, bufa[ss], TILE_BYTES);
                bulk_commit();
                if (i + NL < nt) {              // reuse load slot ls
                    mbar_expect_tx(mb[ls], TILE_BYTES);
                    bulk_load(bufa[ls], xb + (size_t)(t0 + i + NL) * TILE_BYTES, TILE_BYTES, mb[ls]);
                }
            }
        }
        if (tid == 0) bulk_wait_group0();       // drain stores before exit
        __syncthreads();
    }
}

// ---------------------------------------------------------------------------
extern "C" void kernel_launch(void* const* d_in, const int* in_sizes, int n_in,
                              void* d_out, int out_size) {
    const float* x     = (const float*)d_in[0];
    const int*   len_x = (const int*)d_in[1];
    const float* Ww1_w = (const float*)d_in[2];
    const float* Ww1_b = (const float*)d_in[3];
    const float* Ww2_w = (const float*)d_in[4];
    const float* Ww2_b = (const float*)d_in[5];
    const float* Wb1_w = (const float*)d_in[6];
    const float* Wb1_b = (const float*)d_in[7];
    const float* Wb2_w = (const float*)d_in[8];
    const float* Wb2_b = (const float*)d_in[9];
    float* out = (float*)d_out;

    cudaFuncSetAttribute(fused_kernel,
                         cudaFuncAttributeMaxDynamicSharedMemorySize, DYN_SMEM);
    fused_kernel<<<GRID, NTHREADS, DYN_SMEM>>>(
        x, len_x,
        Ww1_w, Ww1_b, Ww2_w, Ww2_b,
        Wb1_w, Wb1_b, Wb2_w, Wb2_b,
        out);
}